// round 15
// baseline (speedup 1.0000x reference)
#include <cuda_runtime.h>
#include <cuda_bf16.h>
#include <cstdint>

// ---------------- problem constants ----------------
#define N_  20000
#define E_  200000
#define T_  3
#define PITCH 36    // node-kernel smem tile pitch (floats)
#define EB  256     // edges per mma tile
#define SP  68      // edge smem pitch (u32)
#define NTILES ((E_ + EB - 1) / EB)   // 782
#define EGRID 296   // persistent edge blocks

// ---------------- persistent device scratch ----------------
__device__ __align__(16) float g_wd[N_];
__device__ __align__(16) float g_cell[N_ * 64];
__device__ __align__(16) float g_dev[N_ * 64];
__device__ __align__(16) float g_y[N_ * 64];
__device__ __align__(16) float g_msg[N_ * 64];
__device__ int g_cnt0[N_ + 1], g_off0[N_ + 1], g_cur0[N_];
__device__ int g_cnt1[N_ + 1], g_off1[N_ + 1], g_cur1[N_];
__device__ int g_pe0[E_], g_pe1[E_];
__device__ int g_q0[E_];
__device__ float g_partial[2];

// ---------------- math helpers ----------------
__device__ __forceinline__ float tanha(float x) {
    float y; asm("tanh.approx.f32 %0, %1;" : "=f"(y) : "f"(x)); return y;
}
__device__ __forceinline__ float sigm_fast(float x) {
    return 0.5f * tanha(0.5f * x) + 0.5f;
}
__device__ __forceinline__ unsigned long long pack2(float a, float b) {
    unsigned long long r; asm("mov.b64 %0, {%1, %2};" : "=l"(r) : "f"(a), "f"(b)); return r;
}
__device__ __forceinline__ void unpack2(unsigned long long v, float& a, float& b) {
    asm("mov.b64 {%0, %1}, %2;" : "=f"(a), "=f"(b) : "l"(v));
}
__device__ __forceinline__ void fma2(unsigned long long& d, unsigned long long a, unsigned long long b) {
    asm("fma.rn.f32x2 %0, %1, %2, %0;" : "+l"(d) : "l"(a), "l"(b));
}
__device__ __forceinline__ uint32_t f2tf32(float x) {
    uint32_t u; asm("cvt.rna.tf32.f32 %0, %1;" : "=r"(u) : "f"(x)); return u;
}

// m16n8k8 tf32 mma
__device__ __forceinline__ void mma_tf32(float* c, const uint32_t* a, uint32_t b0, uint32_t b1) {
    asm volatile("mma.sync.aligned.m16n8k8.row.col.f32.tf32.tf32.f32 "
        "{%0,%1,%2,%3}, {%4,%5,%6,%7}, {%8,%9}, {%0,%1,%2,%3};"
        : "+f"(c[0]), "+f"(c[1]), "+f"(c[2]), "+f"(c[3])
        : "r"(a[0]), "r"(a[1]), "r"(a[2]), "r"(a[3]), "r"(b0), "r"(b1));
}

// Packed-f32x2 register-tile GEMM (fp32 node paths)
template<int K, int NP, int PITCHX>
__device__ __forceinline__ void gemm2t(const float* in_t, const float* Ws,
                                       float bias, int j, int item0,
                                       unsigned long long* acc) {
    unsigned long long b2 = pack2(bias, bias);
#pragma unroll
    for (int p = 0; p < NP; p++) acc[p] = b2;
    const float* col = in_t + item0;
#pragma unroll 8
    for (int k = 0; k < K; k++) {
        float w = Ws[k * 64 + j];
        unsigned long long ww = pack2(w, w);
        const ulonglong2* row = reinterpret_cast<const ulonglong2*>(col + k * PITCHX);
#pragma unroll
        for (int p = 0; p < NP / 2; p++) {
            ulonglong2 v = row[p];
            fma2(acc[2 * p],     v.x, ww);
            fma2(acc[2 * p + 1], v.y, ww);
        }
    }
}

// ---------------- setup kernels (round-8 exact) ----------------
__global__ void init_kernel(const float* __restrict__ cell_d,
                            float* __restrict__ out, int out_size) {
    int i = blockIdx.x * blockDim.x + threadIdx.x;
    if (i < N_ * 64) g_dev[i] = 0.f;
    if (i < N_) {
        g_wd[i] = cell_d[i * 12];
        g_cnt0[i] = 0; g_cnt1[i] = 0;
    }
    int ntt = N_ * T_;
    if (i < ntt) {
        int pos = ntt + 1 + i;
        if (pos < out_size) out[pos] = 1.0f;
    }
    if (i == 0) {
        g_cnt0[N_] = 0; g_cnt1[N_] = 0;
        g_partial[0] = 0.f; g_partial[1] = 0.f;
    }
}

__global__ void hist_kernel(const int* __restrict__ ei) {
    int i = blockIdx.x * blockDim.x + threadIdx.x;
    if (i < E_) {
        atomicAdd(&g_cnt0[ei[i]], 1);
        atomicAdd(&g_cnt1[ei[E_ + i]], 1);
    }
}

__global__ void __launch_bounds__(1024) scan_kernel() {
    __shared__ int wsum[32];
    const int CH = 20;
    int tid = threadIdx.x, lane = tid & 31, wid = tid >> 5;
    for (int a = 0; a < 2; a++) {
        const int* c = a ? g_cnt1 : g_cnt0;
        int* o   = a ? g_off1 : g_off0;
        int* cur = a ? g_cur1 : g_cur0;
        int start = tid * CH;
        int vals[CH];
        int s = 0;
#pragma unroll
        for (int i = 0; i < CH; i++) {
            int idx = start + i;
            int v = (idx < N_) ? c[idx] : 0;
            vals[i] = s; s += v;
        }
        int incl = s;
#pragma unroll
        for (int off = 1; off < 32; off <<= 1) {
            int v = __shfl_up_sync(0xffffffffu, incl, off);
            if (lane >= off) incl += v;
        }
        if (lane == 31) wsum[wid] = incl;
        __syncthreads();
        if (wid == 0) {
            int v = wsum[lane];
            int e = v;
#pragma unroll
            for (int off = 1; off < 32; off <<= 1) {
                int u = __shfl_up_sync(0xffffffffu, e, off);
                if (lane >= off) e += u;
            }
            wsum[lane] = e - v;
        }
        __syncthreads();
        int texcl = wsum[wid] + incl - s;
#pragma unroll
        for (int i = 0; i < CH; i++) {
            int idx = start + i;
            if (idx < N_) {
                int val = texcl + vals[i];
                o[idx] = val; cur[idx] = val;
            }
        }
        if (tid == 1023) o[N_] = texcl + s;
        __syncthreads();
    }
}

__global__ void fill_kernel(const int* __restrict__ ei) {
    int i = blockIdx.x * blockDim.x + threadIdx.x;
    if (i < E_) {
        int a = ei[i], b = ei[E_ + i];
        int s0 = atomicAdd(&g_cur0[a], 1);
        g_pe0[s0] = a; g_pe1[s0] = b;
        int s1 = atomicAdd(&g_cur1[b], 1);
        g_q0[s1] = a;
    }
}

// ---------------- fused node kernels (round-8 proven) ----------------
__device__ __forceinline__ void pre_part(float* in_t, const float* C1, const float* C2,
                                         const float* cb1s, const float* cb2s,
                                         const float* dWs, const float* dBs,
                                         const float* dem_sh, int base, int j, int g) {
#pragma unroll
    for (int i = 0; i < 8; i++) {
        int item = g * 8 + i;
        g_y[(base + item) * 64 + j] = in_t[j * PITCH + item] + dem_sh[item] * dWs[j] + dBs[j];
    }
    unsigned long long acc[4];
    gemm2t<64, 4, PITCH>(in_t, C1, cb1s[j], j, g * 8, acc);
    __syncthreads();
#pragma unroll
    for (int p = 0; p < 4; p++) {
        float lo, hi; unpack2(acc[p], lo, hi);
        *reinterpret_cast<unsigned long long*>(in_t + j * PITCH + g * 8 + 2 * p)
            = pack2(tanha(lo), tanha(hi));
    }
    __syncthreads();
    gemm2t<64, 4, PITCH>(in_t, C2, cb2s[j], j, g * 8, acc);
#pragma unroll
    for (int p = 0; p < 4; p++) {
        float lo, hi; unpack2(acc[p], lo, hi);
        g_msg[(base + g * 8 + 2 * p) * 64 + j]     = lo;
        g_msg[(base + g * 8 + 2 * p + 1) * 64 + j] = hi;
    }
}

__device__ __forceinline__ void dql_part(float* in_t, const float* Wds, const float* bds,
                                         float* dsw, int base, int w, int lane, int do_tanh) {
#pragma unroll
    for (int r = 0; r < 4; r++) {
        int e = w * 4 + r;
        int node = base + e;
        float i0 = 0.f, i1 = 0.f;
        int s0 = g_off1[node], s1 = g_off1[node + 1];
        for (int s = s0; s < s1; s++) {
            int m = g_q0[s];
            i0 += g_dev[m * 64 + lane];
            i1 += g_dev[m * 64 + 32 + lane];
        }
        float d0 = i0 - g_dev[node * 64 + lane];
        float d1 = i1 - g_dev[node * 64 + 32 + lane];
        dsw[lane] = d0; dsw[32 + lane] = d1;
        __syncwarp();
        float a0 = bds[lane], a1 = bds[32 + lane];
#pragma unroll 4
        for (int k = 0; k < 64; k++) {
            float dv = dsw[k];
            a0 = fmaf(dv, Wds[k * 64 + lane], a0);
            a1 = fmaf(dv, Wds[k * 64 + 32 + lane], a1);
        }
        float c0 = g_cell[node * 64 + lane] + a0;
        float c1 = g_cell[node * 64 + 32 + lane] + a1;
        if (do_tanh) { c0 = tanha(c0); c1 = tanha(c1); }
        g_cell[node * 64 + lane] = c0;
        g_cell[node * 64 + 32 + lane] = c1;
        in_t[lane * PITCH + e] = c0;
        in_t[(lane + 32) * PITCH + e] = c1;
        __syncwarp();
    }
}

// rain (3 layers) + conservation-0 pre (y, msg)
#define RP_SMEM ((2304 + 2048 + 4096 * 3 + 64 * 6 + 32) * 4)
__global__ void __launch_bounds__(256) rainpre_kernel(
    const float* __restrict__ cell_d, const float* __restrict__ cell_s,
    const float* __restrict__ rW1, const float* __restrict__ rb1,
    const float* __restrict__ rW2, const float* __restrict__ rb2,
    const float* __restrict__ rW3, const float* __restrict__ rb3,
    const float* __restrict__ demW, const float* __restrict__ demb,
    const float* __restrict__ cW1, const float* __restrict__ cb1,
    const float* __restrict__ cW2, const float* __restrict__ cb2, int t)
{
    extern __shared__ __align__(16) float sf[];
    float* in_t = sf;
    float* W2r = sf + 2304;
    float* W3r = sf + 4352;
    float* C1  = sf + 8448;
    float* C2  = sf + 12544;
    float* b2r = sf + 16640;
    float* b3r = sf + 16704;
    float* cb1s = sf + 16768;
    float* cb2s = sf + 16832;
    float* dWs = sf + 16896;
    float* dBs = sf + 16960;
    float* dem_sh = sf + 17024;
    int tid = threadIdx.x;
    int base = blockIdx.x * 32;
    for (int i = tid; i < 2048; i += 256) W2r[i] = rW2[i];
    for (int i = tid; i < 4096; i += 256) { W3r[i] = rW3[i]; C1[i] = cW1[i]; C2[i] = cW2[i]; }
    if (tid < 64) {
        b2r[tid] = rb2[tid]; b3r[tid] = rb3[tid];
        cb1s[tid] = cb1[tid]; cb2s[tid] = cb2[tid];
        dWs[tid] = demW[tid]; dBs[tid] = demb[tid];
    }
    if (tid < 32) dem_sh[tid] = cell_s[(base + tid) * 2];
    {
        int e = tid & 31, fb = tid >> 5;
        int n = base + e;
        float w = g_wd[n];
        float r = cell_d[n * 12 + t * 3 + 2];
#pragma unroll
        for (int u = 0; u < 4; u++) {
            int f = fb * 4 + u;
            in_t[f * PITCH + e] = tanha(w * rW1[f] + r * rW1[32 + f] + rb1[f]);
        }
    }
    __syncthreads();
    int j = tid & 63, g = tid >> 6;
    unsigned long long acc[4];
    gemm2t<32, 4, PITCH>(in_t, W2r, b2r[j], j, g * 8, acc);
    __syncthreads();
#pragma unroll
    for (int p = 0; p < 4; p++) {
        float lo, hi; unpack2(acc[p], lo, hi);
        *reinterpret_cast<unsigned long long*>(in_t + j * PITCH + g * 8 + 2 * p)
            = pack2(tanha(lo), tanha(hi));
    }
    __syncthreads();
    gemm2t<64, 4, PITCH>(in_t, W3r, b3r[j], j, g * 8, acc);
    __syncthreads();
#pragma unroll
    for (int p = 0; p < 4; p++) {
        float lo, hi; unpack2(acc[p], lo, hi);
        int i0 = g * 8 + 2 * p;
        g_cell[(base + i0) * 64 + j] = lo;
        g_cell[(base + i0 + 1) * 64 + j] = hi;
        in_t[j * PITCH + i0] = lo;
        in_t[j * PITCH + i0 + 1] = hi;
    }
    __syncthreads();
    pre_part(in_t, C1, C2, cb1s, cb2s, dWs, dBs, dem_sh, base, j, g);
}

// dql(c=0, tanh) + conservation-1 pre
#define DP_SMEM ((2304 + 4096 * 3 + 512 + 64 * 5 + 32) * 4)
__global__ void __launch_bounds__(256) dqlpre_kernel(
    const float* __restrict__ cell_s,
    const float* __restrict__ dqW, const float* __restrict__ dqb,
    const float* __restrict__ demW, const float* __restrict__ demb,
    const float* __restrict__ cW1, const float* __restrict__ cb1,
    const float* __restrict__ cW2, const float* __restrict__ cb2)
{
    extern __shared__ __align__(16) float sf[];
    float* in_t = sf;
    float* Wds = sf + 2304;
    float* C1  = sf + 6400;
    float* C2  = sf + 10496;
    float* ds  = sf + 14592;
    float* bds = sf + 15104;
    float* cb1s = sf + 15168;
    float* cb2s = sf + 15232;
    float* dWs = sf + 15296;
    float* dBs = sf + 15360;
    float* dem_sh = sf + 15424;
    int tid = threadIdx.x;
    int base = blockIdx.x * 32;
    for (int i = tid; i < 4096; i += 256) { Wds[i] = dqW[i]; C1[i] = cW1[i]; C2[i] = cW2[i]; }
    if (tid < 64) {
        bds[tid] = dqb[tid];
        cb1s[tid] = cb1[tid]; cb2s[tid] = cb2[tid];
        dWs[tid] = demW[tid]; dBs[tid] = demb[tid];
    }
    if (tid < 32) dem_sh[tid] = cell_s[(base + tid) * 2];
    __syncthreads();
    int w = tid >> 5, lane = tid & 31;
    dql_part(in_t, Wds, bds, ds + w * 64, base, w, lane, 1);
    __syncthreads();
    int j = tid & 63, g = tid >> 6;
    pre_part(in_t, C1, C2, cb1s, cb2s, dWs, dBs, dem_sh, base, j, g);
}

// dql(c=1, no tanh) + elev + losses
#define DE_SMEM ((2304 + 4096 * 2 + 512 + 64 * 3 + 1) * 4)
__global__ void __launch_bounds__(256) dqlelev_kernel(
    const float* __restrict__ cell_d,
    const float* __restrict__ dqW, const float* __restrict__ dqb,
    const float* __restrict__ eW1, const float* __restrict__ eb1,
    const float* __restrict__ eW2, const float* __restrict__ eb2,
    float* __restrict__ out, int t, int out_size)
{
    extern __shared__ __align__(16) float sf[];
    float* in_t = sf;
    float* Wds = sf + 2304;
    float* W1s = sf + 6400;
    float* ds  = sf + 10496;
    float* bds = sf + 11008;
    float* b1s = sf + 11072;
    float* w2s = sf + 11136;
    float* b2p = sf + 11200;
    int tid = threadIdx.x;
    int base = blockIdx.x * 32;
    for (int i = tid; i < 4096; i += 256) { Wds[i] = dqW[i]; W1s[i] = eW1[i]; }
    if (tid < 64) {
        bds[tid] = dqb[tid];
        b1s[tid] = eb1[tid]; w2s[tid] = eW2[tid];
    }
    if (tid == 0) b2p[0] = eb2[0];
    __syncthreads();
    int w = tid >> 5, lane = tid & 31;
    dql_part(in_t, Wds, bds, ds + w * 64, base, w, lane, 0);
    __syncthreads();
    int j = tid & 63, g = tid >> 6;
    unsigned long long acc[4];
    gemm2t<64, 4, PITCH>(in_t, W1s, b1s[j], j, g * 8, acc);
    __syncthreads();
#pragma unroll
    for (int p = 0; p < 4; p++) {
        float lo, hi; unpack2(acc[p], lo, hi);
        *reinterpret_cast<unsigned long long*>(in_t + j * PITCH + g * 8 + 2 * p)
            = pack2(tanha(lo), tanha(hi));
    }
    __syncthreads();
    if (tid < 32) {
        int e = tid, n = base + e;
        float a = b2p[0];
#pragma unroll 8
        for (int k = 0; k < 64; k++) a = fmaf(in_t[k * PITCH + e], w2s[k], a);
        float wv = g_wd[n] + a;
        g_wd[n] = wv;
        int pos = n * 3 + t;
        if (pos < out_size) out[pos] = wv;
        float target = cell_d[n * 12 + (t + 1) * 3];
        float diff = target - wv;
        float ad = fabsf(diff);
        float hub = (ad < 1.f) ? ad : diff * diff;
        float nz = fmaxf(-wv, 0.f);
#pragma unroll
        for (int o = 16; o > 0; o >>= 1) {
            hub += __shfl_down_sync(0xffffffffu, hub, o);
            nz  += __shfl_down_sync(0xffffffffu, nz, o);
        }
        if (e == 0) {
            atomicAdd(&g_partial[0], hub);
            atomicAdd(&g_partial[1], nz);
        }
    }
}

// ---------------- persistent mma.sync tf32 edge gate kernel ----------------
// Segmented reduction now scales partial gate-sums by msg and accumulates
// DIRECTLY into g_dev (dev_old already present) — devupd kernel eliminated.
#define ES_S   0
#define ES_W1  (256 * SP)
#define ES_W2  (ES_W1 + 4096)
#define ES_B1  (ES_W2 + 4096)
#define ES_B2  (ES_B1 + 64)
#define ES_NID (ES_B2 + 64)
#define E_SMEM ((ES_NID + 256) * 4)

__global__ void __launch_bounds__(256, 2) edge_gate_mma_kernel(
    const float* __restrict__ gW1, const float* __restrict__ gb1,
    const float* __restrict__ gW2, const float* __restrict__ gb2)
{
    extern __shared__ __align__(16) uint32_t sm[];
    uint32_t* S = sm + ES_S;
    uint2* W1b = reinterpret_cast<uint2*>(sm + ES_W1);
    uint2* W2b = reinterpret_cast<uint2*>(sm + ES_W2);
    float* b1s = reinterpret_cast<float*>(sm + ES_B1);
    float* b2s = reinterpret_cast<float*>(sm + ES_B2);
    int* nid = reinterpret_cast<int*>(sm + ES_NID);

    int tid = threadIdx.x;
    for (int i = tid; i < 2048; i += 256) {
        int l = i & 31, ksnt = i >> 5;
        int nt = ksnt >> 3, ks = ksnt & 7;
        int n = nt * 8 + (l >> 2);
        int k0 = ks * 8 + (l & 3);
        W1b[i] = make_uint2(f2tf32(gW1[k0 * 64 + n]), f2tf32(gW1[(k0 + 4) * 64 + n]));
        W2b[i] = make_uint2(f2tf32(gW2[k0 * 64 + n]), f2tf32(gW2[(k0 + 4) * 64 + n]));
    }
    if (tid < 64) { b1s[tid] = gb1[tid]; b2s[tid] = gb2[tid]; }

    int w = tid >> 5, l = tid & 31;
    int g = l >> 2, t = l & 3;
    int erow = w * 32;

    for (int tile = blockIdx.x; tile < NTILES; tile += gridDim.x) {
        __syncthreads();
        int base = tile * EB;
#pragma unroll
        for (int eo = 0; eo < EB; eo += 128) {
            int e = (tid >> 1) + eo, half = tid & 1;
            int slot = base + e;
            int c0 = half * 32;
            if (slot < E_) {
                int n0 = g_pe0[slot], n1 = g_pe1[slot];
                if (half == 0) nid[e] = n0;
                const float4* pa = reinterpret_cast<const float4*>(g_y + n0 * 64 + c0);
                const float4* pc = reinterpret_cast<const float4*>(g_y + n1 * 64 + c0);
#pragma unroll
                for (int q = 0; q < 8; q++) {
                    float4 a = pa[q], c = pc[q];
                    uint4 v;
                    v.x = f2tf32(a.x - c.x); v.y = f2tf32(a.y - c.y);
                    v.z = f2tf32(a.z - c.z); v.w = f2tf32(a.w - c.w);
                    *reinterpret_cast<uint4*>(S + e * SP + c0 + q * 4) = v;
                }
            } else {
                if (half == 0) nid[e] = -1;
                uint4 z = {0u, 0u, 0u, 0u};
#pragma unroll
                for (int q = 0; q < 8; q++)
                    *reinterpret_cast<uint4*>(S + e * SP + c0 + q * 4) = z;
            }
        }
        __syncthreads();

        uint32_t a[2][8][4];
#pragma unroll
        for (int rg = 0; rg < 2; rg++)
#pragma unroll
            for (int ks = 0; ks < 8; ks++) {
                const uint32_t* p = S + (erow + rg * 16 + g) * SP + t + ks * 8;
                a[rg][ks][0] = p[0];
                a[rg][ks][1] = p[8 * SP];
                a[rg][ks][2] = p[4];
                a[rg][ks][3] = p[8 * SP + 4];
            }
#pragma unroll
        for (int nt = 0; nt < 8; nt++) {
            uint2 b[8];
#pragma unroll
            for (int ks = 0; ks < 8; ks++) b[ks] = W1b[((nt * 8 + ks) << 5) + l];
            float bl = b1s[nt * 8 + 2 * t], bh = b1s[nt * 8 + 2 * t + 1];
#pragma unroll
            for (int rg = 0; rg < 2; rg++) {
                float acc[4] = {bl, bh, bl, bh};
#pragma unroll
                for (int ks = 0; ks < 8; ks++)
                    mma_tf32(acc, a[rg][ks], b[ks].x, b[ks].y);
                uint32_t* s0 = S + (erow + rg * 16 + g) * SP + nt * 8 + 2 * t;
                *reinterpret_cast<uint2*>(s0) = make_uint2(f2tf32(tanha(acc[0])), f2tf32(tanha(acc[1])));
                *reinterpret_cast<uint2*>(s0 + 8 * SP) = make_uint2(f2tf32(tanha(acc[2])), f2tf32(tanha(acc[3])));
            }
        }
        __syncwarp();
#pragma unroll
        for (int rg = 0; rg < 2; rg++)
#pragma unroll
            for (int ks = 0; ks < 8; ks++) {
                const uint32_t* p = S + (erow + rg * 16 + g) * SP + t + ks * 8;
                a[rg][ks][0] = p[0];
                a[rg][ks][1] = p[8 * SP];
                a[rg][ks][2] = p[4];
                a[rg][ks][3] = p[8 * SP + 4];
            }
#pragma unroll
        for (int nt = 0; nt < 8; nt++) {
            uint2 b[8];
#pragma unroll
            for (int ks = 0; ks < 8; ks++) b[ks] = W2b[((nt * 8 + ks) << 5) + l];
            float bl = b2s[nt * 8 + 2 * t], bh = b2s[nt * 8 + 2 * t + 1];
#pragma unroll
            for (int rg = 0; rg < 2; rg++) {
                float acc[4] = {bl, bh, bl, bh};
#pragma unroll
                for (int ks = 0; ks < 8; ks++)
                    mma_tf32(acc, a[rg][ks], b[ks].x, b[ks].y);
                uint32_t* s0 = S + (erow + rg * 16 + g) * SP + nt * 8 + 2 * t;
                *reinterpret_cast<uint2*>(s0) = make_uint2(__float_as_uint(sigm_fast(acc[0])),
                                                           __float_as_uint(sigm_fast(acc[1])));
                *reinterpret_cast<uint2*>(s0 + 8 * SP) = make_uint2(__float_as_uint(sigm_fast(acc[2])),
                                                                    __float_as_uint(sigm_fast(acc[3])));
            }
        }
        __syncthreads();
        // segmented column reduction -> dev += msg * (segment gate sum), atomically
        {
            int col = tid & 63, q = tid >> 6;
            int r0 = q * 64, r1 = r0 + 64;
            float accv = 0.f;
            int cur = nid[r0];
#pragma unroll 8
            for (int r = r0; r < r1; r++) {
                int nd = nid[r];
                float v = __uint_as_float(S[r * SP + col]);
                if (nd != cur) {
                    if (cur >= 0)
                        atomicAdd(g_dev + (size_t)cur * 64 + col,
                                  accv * g_msg[(size_t)cur * 64 + col]);
                    accv = 0.f; cur = nd;
                }
                accv += v;
            }
            if (cur >= 0)
                atomicAdd(g_dev + (size_t)cur * 64 + col,
                          accv * g_msg[(size_t)cur * 64 + col]);
        }
    }
}

__global__ void tail_kernel(float* __restrict__ out, int out_size) {
    int ntt = N_ * T_;
    if (ntt < out_size)         out[ntt]         = g_partial[0] * (0.5f / (float)N_);
    if (2 * ntt + 1 < out_size) out[2 * ntt + 1] = g_partial[1] * (1.0f / (float)N_);
}

// ---------------- launcher ----------------
extern "C" void kernel_launch(void* const* d_in, const int* in_sizes, int n_in,
                              void* d_out, int out_size) {
    const float* cell_d = (const float*)d_in[0];
    const float* cell_s = (const float*)d_in[1];
    const int*   eidx   = (const int*)d_in[3];
    const float* rW1 = (const float*)d_in[5];
    const float* rb1 = (const float*)d_in[6];
    const float* rW2 = (const float*)d_in[7];
    const float* rb2 = (const float*)d_in[8];
    const float* rW3 = (const float*)d_in[9];
    const float* rb3 = (const float*)d_in[10];
    const float* eW1 = (const float*)d_in[11];
    const float* eb1 = (const float*)d_in[12];
    const float* eW2 = (const float*)d_in[13];
    const float* eb2 = (const float*)d_in[14];
    const float* demW = (const float*)d_in[15];
    const float* demb = (const float*)d_in[16];
    const float* cW1 = (const float*)d_in[17];
    const float* cb1 = (const float*)d_in[18];
    const float* cW2 = (const float*)d_in[19];
    const float* cb2 = (const float*)d_in[20];
    const float* gW1 = (const float*)d_in[21];
    const float* gb1 = (const float*)d_in[22];
    const float* gW2 = (const float*)d_in[23];
    const float* gb2 = (const float*)d_in[24];
    const float* dqW = (const float*)d_in[25];
    const float* dqb = (const float*)d_in[26];
    float* out = (float*)d_out;

    cudaFuncSetAttribute(edge_gate_mma_kernel,
                         cudaFuncAttributeMaxDynamicSharedMemorySize, E_SMEM);
    cudaFuncSetAttribute(rainpre_kernel,
                         cudaFuncAttributeMaxDynamicSharedMemorySize, RP_SMEM);
    cudaFuncSetAttribute(dqlpre_kernel,
                         cudaFuncAttributeMaxDynamicSharedMemorySize, DP_SMEM);
    cudaFuncSetAttribute(dqlelev_kernel,
                         cudaFuncAttributeMaxDynamicSharedMemorySize, DE_SMEM);

    init_kernel<<<(N_ * 64 + 255) / 256, 256>>>(cell_d, out, out_size);
    hist_kernel<<<(E_ + 255) / 256, 256>>>(eidx);
    scan_kernel<<<1, 1024>>>();
    fill_kernel<<<(E_ + 255) / 256, 256>>>(eidx);

    const int nodeBlocks = N_ / 32;   // 625

    for (int t = 0; t < T_; t++) {
        rainpre_kernel<<<nodeBlocks, 256, RP_SMEM>>>(cell_d, cell_s,
            rW1, rb1, rW2, rb2, rW3, rb3,
            demW, demb, cW1, cb1, cW2, cb2, t);
        edge_gate_mma_kernel<<<EGRID, 256, E_SMEM>>>(gW1, gb1, gW2, gb2);
        dqlpre_kernel<<<nodeBlocks, 256, DP_SMEM>>>(cell_s,
            dqW, dqb,
            demW + 64, demb + 64, cW1 + 4096, cb1 + 64, cW2 + 4096, cb2 + 64);
        edge_gate_mma_kernel<<<EGRID, 256, E_SMEM>>>(gW1 + 4096, gb1 + 64, gW2 + 4096, gb2 + 64);
        dqlelev_kernel<<<nodeBlocks, 256, DE_SMEM>>>(cell_d,
            dqW + 4096, dqb + 64, eW1, eb1, eW2, eb2, out, t, out_size);
    }
    tail_kernel<<<1, 1>>>(out, out_size);
}

// round 16
// speedup vs baseline: 1.0282x; 1.0282x over previous
#include <cuda_runtime.h>
#include <cuda_bf16.h>
#include <cstdint>

// ---------------- problem constants ----------------
#define N_  20000
#define E_  200000
#define T_  3
#define NPITCH 68   // node-kernel smem tile pitch (floats)
#define NT  64      // nodes per node-kernel block
#define NBLK ((N_ + NT - 1) / NT)     // 313
#define EB  256     // edges per mma tile
#define SP  68      // edge smem pitch (u32)
#define NTILES ((E_ + EB - 1) / EB)   // 782
#define EGRID 296   // persistent edge blocks

// ---------------- persistent device scratch ----------------
__device__ __align__(16) float g_wd[N_];
__device__ __align__(16) float g_cell[N_ * 64];
__device__ __align__(16) float g_dev[N_ * 64];
__device__ __align__(16) float g_u[N_ * 64];    // u = (cell + dem_e) @ gate_W1[c]
__device__ __align__(16) float g_msg[N_ * 64];
__device__ __align__(16) float g_gs[N_ * 64];
__device__ int g_cnt0[N_ + 1], g_off0[N_ + 1], g_cur0[N_];
__device__ int g_cnt1[N_ + 1], g_off1[N_ + 1], g_cur1[N_];
__device__ int g_pe0[E_], g_pe1[E_];
__device__ int g_q0[E_];
__device__ float g_partial[2];

// ---------------- math helpers ----------------
__device__ __forceinline__ float tanha(float x) {
    float y; asm("tanh.approx.f32 %0, %1;" : "=f"(y) : "f"(x)); return y;
}
__device__ __forceinline__ float sigm_fast(float x) {
    return 0.5f * tanha(0.5f * x) + 0.5f;
}
__device__ __forceinline__ unsigned long long pack2(float a, float b) {
    unsigned long long r; asm("mov.b64 %0, {%1, %2};" : "=l"(r) : "f"(a), "f"(b)); return r;
}
__device__ __forceinline__ void unpack2(unsigned long long v, float& a, float& b) {
    asm("mov.b64 {%0, %1}, %2;" : "=f"(a), "=f"(b) : "l"(v));
}
__device__ __forceinline__ void fma2(unsigned long long& d, unsigned long long a, unsigned long long b) {
    asm("fma.rn.f32x2 %0, %1, %2, %0;" : "+l"(d) : "l"(a), "l"(b));
}
__device__ __forceinline__ uint32_t f2tf32(float x) {
    uint32_t u; asm("cvt.rna.tf32.f32 %0, %1;" : "=r"(u) : "f"(x)); return u;
}

// m16n8k8 tf32 mma
__device__ __forceinline__ void mma_tf32(float* c, const uint32_t* a, uint32_t b0, uint32_t b1) {
    asm volatile("mma.sync.aligned.m16n8k8.row.col.f32.tf32.tf32.f32 "
        "{%0,%1,%2,%3}, {%4,%5,%6,%7}, {%8,%9}, {%0,%1,%2,%3};"
        : "+f"(c[0]), "+f"(c[1]), "+f"(c[2]), "+f"(c[3])
        : "r"(a[0]), "r"(a[1]), "r"(a[2]), "r"(a[3]), "r"(b0), "r"(b1));
}

// Packed-f32x2 register-tile GEMM
template<int K, int NP, int PITCHX>
__device__ __forceinline__ void gemm2t(const float* in_t, const float* Ws,
                                       float bias, int j, int item0,
                                       unsigned long long* acc) {
    unsigned long long b2 = pack2(bias, bias);
#pragma unroll
    for (int p = 0; p < NP; p++) acc[p] = b2;
    const float* col = in_t + item0;
#pragma unroll 8
    for (int k = 0; k < K; k++) {
        float w = Ws[k * 64 + j];
        unsigned long long ww = pack2(w, w);
        const ulonglong2* row = reinterpret_cast<const ulonglong2*>(col + k * PITCHX);
#pragma unroll
        for (int p = 0; p < NP / 2; p++) {
            ulonglong2 v = row[p];
            fma2(acc[2 * p],     v.x, ww);
            fma2(acc[2 * p + 1], v.y, ww);
        }
    }
}

// ---------------- setup kernels (round-8 exact) ----------------
__global__ void init_kernel(const float* __restrict__ cell_d,
                            float* __restrict__ out, int out_size) {
    int i = blockIdx.x * blockDim.x + threadIdx.x;
    if (i < N_ * 64) { g_dev[i] = 0.f; g_gs[i] = 0.f; }
    if (i < N_) {
        g_wd[i] = cell_d[i * 12];
        g_cnt0[i] = 0; g_cnt1[i] = 0;
    }
    int ntt = N_ * T_;
    if (i < ntt) {
        int pos = ntt + 1 + i;
        if (pos < out_size) out[pos] = 1.0f;
    }
    if (i == 0) {
        g_cnt0[N_] = 0; g_cnt1[N_] = 0;
        g_partial[0] = 0.f; g_partial[1] = 0.f;
    }
}

__global__ void hist_kernel(const int* __restrict__ ei) {
    int i = blockIdx.x * blockDim.x + threadIdx.x;
    if (i < E_) {
        atomicAdd(&g_cnt0[ei[i]], 1);
        atomicAdd(&g_cnt1[ei[E_ + i]], 1);
    }
}

__global__ void __launch_bounds__(1024) scan_kernel() {
    __shared__ int wsum[32];
    const int CH = 20;
    int tid = threadIdx.x, lane = tid & 31, wid = tid >> 5;
    for (int a = 0; a < 2; a++) {
        const int* c = a ? g_cnt1 : g_cnt0;
        int* o   = a ? g_off1 : g_off0;
        int* cur = a ? g_cur1 : g_cur0;
        int start = tid * CH;
        int vals[CH];
        int s = 0;
#pragma unroll
        for (int i = 0; i < CH; i++) {
            int idx = start + i;
            int v = (idx < N_) ? c[idx] : 0;
            vals[i] = s; s += v;
        }
        int incl = s;
#pragma unroll
        for (int off = 1; off < 32; off <<= 1) {
            int v = __shfl_up_sync(0xffffffffu, incl, off);
            if (lane >= off) incl += v;
        }
        if (lane == 31) wsum[wid] = incl;
        __syncthreads();
        if (wid == 0) {
            int v = wsum[lane];
            int e = v;
#pragma unroll
            for (int off = 1; off < 32; off <<= 1) {
                int u = __shfl_up_sync(0xffffffffu, e, off);
                if (lane >= off) e += u;
            }
            wsum[lane] = e - v;
        }
        __syncthreads();
        int texcl = wsum[wid] + incl - s;
#pragma unroll
        for (int i = 0; i < CH; i++) {
            int idx = start + i;
            if (idx < N_) {
                int val = texcl + vals[i];
                o[idx] = val; cur[idx] = val;
            }
        }
        if (tid == 1023) o[N_] = texcl + s;
        __syncthreads();
    }
}

__global__ void fill_kernel(const int* __restrict__ ei) {
    int i = blockIdx.x * blockDim.x + threadIdx.x;
    if (i < E_) {
        int a = ei[i], b = ei[E_ + i];
        int s0 = atomicAdd(&g_cur0[a], 1);
        g_pe0[s0] = a; g_pe1[s0] = b;
        int s1 = atomicAdd(&g_cur1[b], 1);
        g_q0[s1] = a;
    }
}

// ---------------- fused node kernels: 64 nodes / 512 threads ----------------
// pre_part: in_t holds cell. Computes:
//   acc1 = cell @ C1 ; in_t <- y = cell + dem*dW + dB ; g_u = y @ G1 ;
//   in_t <- tanh(acc1) ; g_msg = in_t @ C2
__device__ __forceinline__ void pre_part(float* in_t, const float* C1, const float* C2,
                                         const float* G1,
                                         const float* cb1s, const float* cb2s,
                                         const float* dWs, const float* dBs,
                                         const float* dem_sh, int base, int j, int g) {
    unsigned long long acc1[4];
    gemm2t<64, 4, NPITCH>(in_t, C1, cb1s[j], j, g * 8, acc1);
    __syncthreads();
    // cell -> y (in place)
#pragma unroll
    for (int i = 0; i < 8; i++) {
        int item = g * 8 + i;
        in_t[j * NPITCH + item] += dem_sh[item] * dWs[j] + dBs[j];
    }
    __syncthreads();
    unsigned long long acc2[4];
    gemm2t<64, 4, NPITCH>(in_t, G1, 0.f, j, g * 8, acc2);
#pragma unroll
    for (int p = 0; p < 4; p++) {
        float lo, hi; unpack2(acc2[p], lo, hi);
        int n0 = base + g * 8 + 2 * p;
        if (n0 < N_)     g_u[n0 * 64 + j]       = lo;
        if (n0 + 1 < N_) g_u[(n0 + 1) * 64 + j] = hi;
    }
    __syncthreads();   // all reads of y done
#pragma unroll
    for (int p = 0; p < 4; p++) {
        float lo, hi; unpack2(acc1[p], lo, hi);
        *reinterpret_cast<unsigned long long*>(in_t + j * NPITCH + g * 8 + 2 * p)
            = pack2(tanha(lo), tanha(hi));
    }
    __syncthreads();
    gemm2t<64, 4, NPITCH>(in_t, C2, cb2s[j], j, g * 8, acc1);
#pragma unroll
    for (int p = 0; p < 4; p++) {
        float lo, hi; unpack2(acc1[p], lo, hi);
        int n0 = base + g * 8 + 2 * p;
        if (n0 < N_)     g_msg[n0 * 64 + j]       = lo;
        if (n0 + 1 < N_) g_msg[(n0 + 1) * 64 + j] = hi;
    }
}

__device__ __forceinline__ void dql_part(float* in_t, const float* Wds, const float* bds,
                                         float* dsw, int base, int w, int lane, int do_tanh) {
#pragma unroll
    for (int r = 0; r < 4; r++) {
        int e = w * 4 + r;
        int node = base + e;
        if (node < N_) {
            float i0 = 0.f, i1 = 0.f;
            int s0 = g_off1[node], s1 = g_off1[node + 1];
            for (int s = s0; s < s1; s++) {
                int m = g_q0[s];
                i0 += g_dev[m * 64 + lane];
                i1 += g_dev[m * 64 + 32 + lane];
            }
            float d0 = i0 - g_dev[node * 64 + lane];
            float d1 = i1 - g_dev[node * 64 + 32 + lane];
            dsw[lane] = d0; dsw[32 + lane] = d1;
            __syncwarp();
            float a0 = bds[lane], a1 = bds[32 + lane];
#pragma unroll 4
            for (int k = 0; k < 64; k++) {
                float dv = dsw[k];
                a0 = fmaf(dv, Wds[k * 64 + lane], a0);
                a1 = fmaf(dv, Wds[k * 64 + 32 + lane], a1);
            }
            float c0 = g_cell[node * 64 + lane] + a0;
            float c1 = g_cell[node * 64 + 32 + lane] + a1;
            if (do_tanh) { c0 = tanha(c0); c1 = tanha(c1); }
            g_cell[node * 64 + lane] = c0;
            g_cell[node * 64 + 32 + lane] = c1;
            in_t[lane * NPITCH + e] = c0;
            in_t[(lane + 32) * NPITCH + e] = c1;
        } else {
            in_t[lane * NPITCH + e] = 0.f;
            in_t[(lane + 32) * NPITCH + e] = 0.f;
        }
        __syncwarp();
    }
}

// rain (3 layers) + conservation-0 pre (u, msg)
// floats: in_t 4352 | W2r 2048 | W3r 4096 | C1 4096 | C2 4096 | G1 4096 | b 384 | dem 64
#define RP_SMEM ((4352 + 2048 + 4096 * 4 + 384 + 64) * 4)
__global__ void __launch_bounds__(512) rainpre_kernel(
    const float* __restrict__ cell_d, const float* __restrict__ cell_s,
    const float* __restrict__ rW1, const float* __restrict__ rb1,
    const float* __restrict__ rW2, const float* __restrict__ rb2,
    const float* __restrict__ rW3, const float* __restrict__ rb3,
    const float* __restrict__ demW, const float* __restrict__ demb,
    const float* __restrict__ cW1, const float* __restrict__ cb1,
    const float* __restrict__ cW2, const float* __restrict__ cb2,
    const float* __restrict__ gW1, int t)
{
    extern __shared__ __align__(16) float sf[];
    float* in_t = sf;
    float* W2r = sf + 4352;
    float* W3r = sf + 6400;
    float* C1  = sf + 10496;
    float* C2  = sf + 14592;
    float* G1  = sf + 18688;
    float* b2r = sf + 22784;
    float* b3r = sf + 22848;
    float* cb1s = sf + 22912;
    float* cb2s = sf + 22976;
    float* dWs = sf + 23040;
    float* dBs = sf + 23104;
    float* dem_sh = sf + 23168;
    int tid = threadIdx.x;
    int base = blockIdx.x * NT;
    for (int i = tid; i < 2048; i += 512) W2r[i] = rW2[i];
    for (int i = tid; i < 4096; i += 512) {
        W3r[i] = rW3[i]; C1[i] = cW1[i]; C2[i] = cW2[i]; G1[i] = gW1[i];
    }
    if (tid < 64) {
        b2r[tid] = rb2[tid]; b3r[tid] = rb3[tid];
        cb1s[tid] = cb1[tid]; cb2s[tid] = cb2[tid];
        dWs[tid] = demW[tid]; dBs[tid] = demb[tid];
        int n = base + tid;
        dem_sh[tid] = (n < N_) ? cell_s[n * 2] : 0.f;
    }
    {
        int item = tid & 63, fb = tid >> 6;
        int n = base + item;
        float w = 0.f, r = 0.f;
        if (n < N_) { w = g_wd[n]; r = cell_d[n * 12 + t * 3 + 2]; }
#pragma unroll
        for (int u = 0; u < 4; u++) {
            int f = fb * 4 + u;
            in_t[f * NPITCH + item] = tanha(w * rW1[f] + r * rW1[32 + f] + rb1[f]);
        }
    }
    __syncthreads();
    int j = tid & 63, g = tid >> 6;
    unsigned long long acc[4];
    gemm2t<32, 4, NPITCH>(in_t, W2r, b2r[j], j, g * 8, acc);
    __syncthreads();
#pragma unroll
    for (int p = 0; p < 4; p++) {
        float lo, hi; unpack2(acc[p], lo, hi);
        *reinterpret_cast<unsigned long long*>(in_t + j * NPITCH + g * 8 + 2 * p)
            = pack2(tanha(lo), tanha(hi));
    }
    __syncthreads();
    gemm2t<64, 4, NPITCH>(in_t, W3r, b3r[j], j, g * 8, acc);
    __syncthreads();
#pragma unroll
    for (int p = 0; p < 4; p++) {
        float lo, hi; unpack2(acc[p], lo, hi);
        int i0 = g * 8 + 2 * p;
        int n0 = base + i0;
        if (n0 < N_)     g_cell[n0 * 64 + j]       = lo;
        if (n0 + 1 < N_) g_cell[(n0 + 1) * 64 + j] = hi;
        in_t[j * NPITCH + i0] = lo;
        in_t[j * NPITCH + i0 + 1] = hi;
    }
    __syncthreads();
    pre_part(in_t, C1, C2, G1, cb1s, cb2s, dWs, dBs, dem_sh, base, j, g);
}

// dql(c=0, tanh) + conservation-1 pre (u, msg)
// floats: in_t 4352 | Wd 4096 | C1 4096 | C2 4096 | G1 4096 | ds 1024 | b 320 | dem 64
#define DP_SMEM ((4352 + 4096 * 4 + 1024 + 320 + 64) * 4)
__global__ void __launch_bounds__(512) dqlpre_kernel(
    const float* __restrict__ cell_s,
    const float* __restrict__ dqW, const float* __restrict__ dqb,
    const float* __restrict__ demW, const float* __restrict__ demb,
    const float* __restrict__ cW1, const float* __restrict__ cb1,
    const float* __restrict__ cW2, const float* __restrict__ cb2,
    const float* __restrict__ gW1)
{
    extern __shared__ __align__(16) float sf[];
    float* in_t = sf;
    float* Wds = sf + 4352;
    float* C1  = sf + 8448;
    float* C2  = sf + 12544;
    float* G1  = sf + 16640;
    float* ds  = sf + 20736;
    float* bds = sf + 21760;
    float* cb1s = sf + 21824;
    float* cb2s = sf + 21888;
    float* dWs = sf + 21952;
    float* dBs = sf + 22016;
    float* dem_sh = sf + 22080;
    int tid = threadIdx.x;
    int base = blockIdx.x * NT;
    for (int i = tid; i < 4096; i += 512) {
        Wds[i] = dqW[i]; C1[i] = cW1[i]; C2[i] = cW2[i]; G1[i] = gW1[i];
    }
    if (tid < 64) {
        bds[tid] = dqb[tid];
        cb1s[tid] = cb1[tid]; cb2s[tid] = cb2[tid];
        dWs[tid] = demW[tid]; dBs[tid] = demb[tid];
        int n = base + tid;
        dem_sh[tid] = (n < N_) ? cell_s[n * 2] : 0.f;
    }
    __syncthreads();
    int w = tid >> 5, lane = tid & 31;
    dql_part(in_t, Wds, bds, ds + w * 64, base, w, lane, 1);
    __syncthreads();
    int j = tid & 63, g = tid >> 6;
    pre_part(in_t, C1, C2, G1, cb1s, cb2s, dWs, dBs, dem_sh, base, j, g);
}

// dql(c=1, no tanh) + elev + losses (R14 512-thread variant)
#define DE_SMEM ((4352 + 4096 * 2 + 1024 + 192 + 1) * 4)
__global__ void __launch_bounds__(512) dqlelev_kernel(
    const float* __restrict__ cell_d,
    const float* __restrict__ dqW, const float* __restrict__ dqb,
    const float* __restrict__ eW1, const float* __restrict__ eb1,
    const float* __restrict__ eW2, const float* __restrict__ eb2,
    float* __restrict__ out, int t, int out_size)
{
    extern __shared__ __align__(16) float sf[];
    float* in_t = sf;
    float* Wds = sf + 4352;
    float* W1s = sf + 8448;
    float* ds  = sf + 12544;
    float* bds = sf + 13568;
    float* b1s = sf + 13632;
    float* w2s = sf + 13696;
    float* b2p = sf + 13760;
    int tid = threadIdx.x;
    int base = blockIdx.x * NT;
    for (int i = tid; i < 4096; i += 512) { Wds[i] = dqW[i]; W1s[i] = eW1[i]; }
    if (tid < 64) {
        bds[tid] = dqb[tid];
        b1s[tid] = eb1[tid]; w2s[tid] = eW2[tid];
    }
    if (tid == 0) b2p[0] = eb2[0];
    __syncthreads();
    int w = tid >> 5, lane = tid & 31;
    dql_part(in_t, Wds, bds, ds + w * 64, base, w, lane, 0);
    __syncthreads();
    int j = tid & 63, g = tid >> 6;
    unsigned long long acc[4];
    gemm2t<64, 4, NPITCH>(in_t, W1s, b1s[j], j, g * 8, acc);
    __syncthreads();
#pragma unroll
    for (int p = 0; p < 4; p++) {
        float lo, hi; unpack2(acc[p], lo, hi);
        *reinterpret_cast<unsigned long long*>(in_t + j * NPITCH + g * 8 + 2 * p)
            = pack2(tanha(lo), tanha(hi));
    }
    __syncthreads();
    if (tid < 64) {
        int e = tid, n = base + e;
        float hub = 0.f, nz = 0.f;
        if (n < N_) {
            float a = b2p[0];
#pragma unroll 8
            for (int k = 0; k < 64; k++) a = fmaf(in_t[k * NPITCH + e], w2s[k], a);
            float wv = g_wd[n] + a;
            g_wd[n] = wv;
            int pos = n * 3 + t;
            if (pos < out_size) out[pos] = wv;
            float target = cell_d[n * 12 + (t + 1) * 3];
            float diff = target - wv;
            float ad = fabsf(diff);
            hub = (ad < 1.f) ? ad : diff * diff;
            nz = fmaxf(-wv, 0.f);
        }
#pragma unroll
        for (int o = 16; o > 0; o >>= 1) {
            hub += __shfl_down_sync(0xffffffffu, hub, o);
            nz  += __shfl_down_sync(0xffffffffu, nz, o);
        }
        if ((tid & 31) == 0) {
            atomicAdd(&g_partial[0], hub);
            atomicAdd(&g_partial[1], nz);
        }
    }
}

// ---------------- persistent single-layer edge gate kernel ----------------
// A = tanh(u[e0] - u[e1] + b1) staged directly (fp32 math, tf32 storage);
// one mma layer (W2), sigmoid, segmented reduction into g_gs.
// smem (u32): S[256][SP] | W2b[2048 uint2] | b1[64] | b2[64] | nid[256]
#define ES_S   0
#define ES_W2  (256 * SP)
#define ES_B1  (ES_W2 + 4096)
#define ES_B2  (ES_B1 + 64)
#define ES_NID (ES_B2 + 64)
#define E_SMEM ((ES_NID + 256) * 4)

__global__ void __launch_bounds__(256, 2) edge_gate_mma_kernel(
    const float* __restrict__ gb1,
    const float* __restrict__ gW2, const float* __restrict__ gb2)
{
    extern __shared__ __align__(16) uint32_t sm[];
    uint32_t* S = sm + ES_S;
    uint2* W2b = reinterpret_cast<uint2*>(sm + ES_W2);
    float* b1s = reinterpret_cast<float*>(sm + ES_B1);
    float* b2s = reinterpret_cast<float*>(sm + ES_B2);
    int* nid = reinterpret_cast<int*>(sm + ES_NID);

    int tid = threadIdx.x;
    for (int i = tid; i < 2048; i += 256) {
        int l = i & 31, ksnt = i >> 5;
        int nt = ksnt >> 3, ks = ksnt & 7;
        int n = nt * 8 + (l >> 2);
        int k0 = ks * 8 + (l & 3);
        W2b[i] = make_uint2(f2tf32(gW2[k0 * 64 + n]), f2tf32(gW2[(k0 + 4) * 64 + n]));
    }
    if (tid < 64) { b1s[tid] = gb1[tid]; b2s[tid] = gb2[tid]; }

    int w = tid >> 5, l = tid & 31;
    int g = l >> 2, t = l & 3;
    int erow = w * 32;

    for (int tile = blockIdx.x; tile < NTILES; tile += gridDim.x) {
        __syncthreads();
        int base = tile * EB;
        // stage A = tanh(u0 - u1 + b1), tf32
#pragma unroll
        for (int eo = 0; eo < EB; eo += 128) {
            int e = (tid >> 1) + eo, half = tid & 1;
            int slot = base + e;
            int c0 = half * 32;
            if (slot < E_) {
                int n0 = g_pe0[slot], n1 = g_pe1[slot];
                if (half == 0) nid[e] = n0;
                const float4* pa = reinterpret_cast<const float4*>(g_u + n0 * 64 + c0);
                const float4* pc = reinterpret_cast<const float4*>(g_u + n1 * 64 + c0);
#pragma unroll
                for (int q = 0; q < 8; q++) {
                    float4 a = pa[q], c = pc[q];
                    int f = c0 + q * 4;
                    uint4 v;
                    v.x = f2tf32(tanha(a.x - c.x + b1s[f + 0]));
                    v.y = f2tf32(tanha(a.y - c.y + b1s[f + 1]));
                    v.z = f2tf32(tanha(a.z - c.z + b1s[f + 2]));
                    v.w = f2tf32(tanha(a.w - c.w + b1s[f + 3]));
                    *reinterpret_cast<uint4*>(S + e * SP + f) = v;
                }
            } else {
                if (half == 0) nid[e] = -1;
                uint4 z = {0u, 0u, 0u, 0u};
#pragma unroll
                for (int q = 0; q < 8; q++)
                    *reinterpret_cast<uint4*>(S + e * SP + c0 + q * 4) = z;
            }
        }
        __syncthreads();

        // single MMA layer (W2)
        uint32_t a[2][8][4];
#pragma unroll
        for (int rg = 0; rg < 2; rg++)
#pragma unroll
            for (int ks = 0; ks < 8; ks++) {
                const uint32_t* p = S + (erow + rg * 16 + g) * SP + t + ks * 8;
                a[rg][ks][0] = p[0];
                a[rg][ks][1] = p[8 * SP];
                a[rg][ks][2] = p[4];
                a[rg][ks][3] = p[8 * SP + 4];
            }
#pragma unroll
        for (int nt = 0; nt < 8; nt++) {
            uint2 b[8];
#pragma unroll
            for (int ks = 0; ks < 8; ks++) b[ks] = W2b[((nt * 8 + ks) << 5) + l];
            float bl = b2s[nt * 8 + 2 * t], bh = b2s[nt * 8 + 2 * t + 1];
#pragma unroll
            for (int rg = 0; rg < 2; rg++) {
                float acc[4] = {bl, bh, bl, bh};
#pragma unroll
                for (int ks = 0; ks < 8; ks++)
                    mma_tf32(acc, a[rg][ks], b[ks].x, b[ks].y);
                uint32_t* s0 = S + (erow + rg * 16 + g) * SP + nt * 8 + 2 * t;
                *reinterpret_cast<uint2*>(s0) = make_uint2(__float_as_uint(sigm_fast(acc[0])),
                                                           __float_as_uint(sigm_fast(acc[1])));
                *reinterpret_cast<uint2*>(s0 + 8 * SP) = make_uint2(__float_as_uint(sigm_fast(acc[2])),
                                                                    __float_as_uint(sigm_fast(acc[3])));
            }
        }
        __syncthreads();
        // segmented column reduction -> per-node atomic gate sums
        {
            int col = tid & 63, q = tid >> 6;
            int r0 = q * 64, r1 = r0 + 64;
            float accv = 0.f;
            int cur = nid[r0];
#pragma unroll 8
            for (int r = r0; r < r1; r++) {
                int nd = nid[r];
                float v = __uint_as_float(S[r * SP + col]);
                if (nd != cur) {
                    if (cur >= 0) atomicAdd(g_gs + (size_t)cur * 64 + col, accv);
                    accv = 0.f; cur = nd;
                }
                accv += v;
            }
            if (cur >= 0) atomicAdd(g_gs + (size_t)cur * 64 + col, accv);
        }
    }
}

// dev += msg * gs ; gs = 0
__global__ void __launch_bounds__(256) devupd_kernel() {
    int i = blockIdx.x * blockDim.x + threadIdx.x;
    if (i >= N_ * 16) return;
    float4* dv = reinterpret_cast<float4*>(g_dev) + i;
    float4* gs = reinterpret_cast<float4*>(g_gs) + i;
    const float4* ms = reinterpret_cast<const float4*>(g_msg) + i;
    float4 d = *dv, s = *gs, m = *ms;
    d.x = fmaf(m.x, s.x, d.x);
    d.y = fmaf(m.y, s.y, d.y);
    d.z = fmaf(m.z, s.z, d.z);
    d.w = fmaf(m.w, s.w, d.w);
    *dv = d;
    *gs = make_float4(0.f, 0.f, 0.f, 0.f);
}

__global__ void tail_kernel(float* __restrict__ out, int out_size) {
    int ntt = N_ * T_;
    if (ntt < out_size)         out[ntt]         = g_partial[0] * (0.5f / (float)N_);
    if (2 * ntt + 1 < out_size) out[2 * ntt + 1] = g_partial[1] * (1.0f / (float)N_);
}

// ---------------- launcher ----------------
extern "C" void kernel_launch(void* const* d_in, const int* in_sizes, int n_in,
                              void* d_out, int out_size) {
    const float* cell_d = (const float*)d_in[0];
    const float* cell_s = (const float*)d_in[1];
    const int*   eidx   = (const int*)d_in[3];
    const float* rW1 = (const float*)d_in[5];
    const float* rb1 = (const float*)d_in[6];
    const float* rW2 = (const float*)d_in[7];
    const float* rb2 = (const float*)d_in[8];
    const float* rW3 = (const float*)d_in[9];
    const float* rb3 = (const float*)d_in[10];
    const float* eW1 = (const float*)d_in[11];
    const float* eb1 = (const float*)d_in[12];
    const float* eW2 = (const float*)d_in[13];
    const float* eb2 = (const float*)d_in[14];
    const float* demW = (const float*)d_in[15];
    const float* demb = (const float*)d_in[16];
    const float* cW1 = (const float*)d_in[17];
    const float* cb1 = (const float*)d_in[18];
    const float* cW2 = (const float*)d_in[19];
    const float* cb2 = (const float*)d_in[20];
    const float* gW1 = (const float*)d_in[21];
    const float* gb1 = (const float*)d_in[22];
    const float* gW2 = (const float*)d_in[23];
    const float* gb2 = (const float*)d_in[24];
    const float* dqW = (const float*)d_in[25];
    const float* dqb = (const float*)d_in[26];
    float* out = (float*)d_out;

    cudaFuncSetAttribute(edge_gate_mma_kernel,
                         cudaFuncAttributeMaxDynamicSharedMemorySize, E_SMEM);
    cudaFuncSetAttribute(rainpre_kernel,
                         cudaFuncAttributeMaxDynamicSharedMemorySize, RP_SMEM);
    cudaFuncSetAttribute(dqlpre_kernel,
                         cudaFuncAttributeMaxDynamicSharedMemorySize, DP_SMEM);
    cudaFuncSetAttribute(dqlelev_kernel,
                         cudaFuncAttributeMaxDynamicSharedMemorySize, DE_SMEM);

    init_kernel<<<(N_ * 64 + 255) / 256, 256>>>(cell_d, out, out_size);
    hist_kernel<<<(E_ + 255) / 256, 256>>>(eidx);
    scan_kernel<<<1, 1024>>>();
    fill_kernel<<<(E_ + 255) / 256, 256>>>(eidx);

    const int devBlocks = (N_ * 16 + 255) / 256;

    for (int t = 0; t < T_; t++) {
        rainpre_kernel<<<NBLK, 512, RP_SMEM>>>(cell_d, cell_s,
            rW1, rb1, rW2, rb2, rW3, rb3,
            demW, demb, cW1, cb1, cW2, cb2, gW1, t);
        edge_gate_mma_kernel<<<EGRID, 256, E_SMEM>>>(gb1, gW2, gb2);
        devupd_kernel<<<devBlocks, 256>>>();
        dqlpre_kernel<<<NBLK, 512, DP_SMEM>>>(cell_s,
            dqW, dqb,
            demW + 64, demb + 64, cW1 + 4096, cb1 + 64, cW2 + 4096, cb2 + 64,
            gW1 + 4096);
        edge_gate_mma_kernel<<<EGRID, 256, E_SMEM>>>(gb1 + 64, gW2 + 4096, gb2 + 64);
        devupd_kernel<<<devBlocks, 256>>>();
        dqlelev_kernel<<<NBLK, 512, DE_SMEM>>>(cell_d,
            dqW + 4096, dqb + 64, eW1, eb1, eW2, eb2, out, t, out_size);
    }
    tail_kernel<<<1, 1>>>(out, out_size);
}

// round 17
// speedup vs baseline: 1.0788x; 1.0492x over previous
#include <cuda_runtime.h>
#include <cuda_bf16.h>
#include <cstdint>

// ---------------- problem constants ----------------
#define N_  20000
#define E_  200000
#define T_  3
#define NPITCH 68   // node-kernel smem tile pitch (floats)
#define NT  64      // nodes per node-kernel block
#define NBLK ((N_ + NT - 1) / NT)     // 313
#define EB  256     // edges per mma tile
#define SP  68      // edge smem pitch (u32)
#define NTILES ((E_ + EB - 1) / EB)   // 782
#define EGRID 296   // persistent edge blocks

// ---------------- persistent device scratch ----------------
__device__ __align__(16) float g_wd[N_];
__device__ __align__(16) float g_cell[N_ * 64];
__device__ __align__(16) float g_dev[N_ * 64];
__device__ __align__(16) float g_u[N_ * 64];    // u = (cell + dem_e) @ gate_W1[c]
__device__ __align__(16) float g_msg[N_ * 64];
__device__ __align__(16) float g_gs[N_ * 64];
__device__ __align__(16) float g_v1[2 * 64];    // demW[c] @ gW1[c]
__device__ __align__(16) float g_v2[2 * 64];    // demb[c] @ gW1[c]
__device__ int g_cnt0[N_ + 1], g_off0[N_ + 1], g_cur0[N_];
__device__ int g_cnt1[N_ + 1], g_off1[N_ + 1], g_cur1[N_];
__device__ int g_pe0[E_], g_pe1[E_];
__device__ int g_q0[E_];
__device__ float g_partial[2];

// ---------------- math helpers ----------------
__device__ __forceinline__ float tanha(float x) {
    float y; asm("tanh.approx.f32 %0, %1;" : "=f"(y) : "f"(x)); return y;
}
__device__ __forceinline__ float sigm_fast(float x) {
    return 0.5f * tanha(0.5f * x) + 0.5f;
}
__device__ __forceinline__ unsigned long long pack2(float a, float b) {
    unsigned long long r; asm("mov.b64 %0, {%1, %2};" : "=l"(r) : "f"(a), "f"(b)); return r;
}
__device__ __forceinline__ void unpack2(unsigned long long v, float& a, float& b) {
    asm("mov.b64 {%0, %1}, %2;" : "=f"(a), "=f"(b) : "l"(v));
}
__device__ __forceinline__ void fma2(unsigned long long& d, unsigned long long a, unsigned long long b) {
    asm("fma.rn.f32x2 %0, %1, %2, %0;" : "+l"(d) : "l"(a), "l"(b));
}
__device__ __forceinline__ uint32_t f2tf32(float x) {
    uint32_t u; asm("cvt.rna.tf32.f32 %0, %1;" : "=r"(u) : "f"(x)); return u;
}

// m16n8k8 tf32 mma
__device__ __forceinline__ void mma_tf32(float* c, const uint32_t* a, uint32_t b0, uint32_t b1) {
    asm volatile("mma.sync.aligned.m16n8k8.row.col.f32.tf32.tf32.f32 "
        "{%0,%1,%2,%3}, {%4,%5,%6,%7}, {%8,%9}, {%0,%1,%2,%3};"
        : "+f"(c[0]), "+f"(c[1]), "+f"(c[2]), "+f"(c[3])
        : "r"(a[0]), "r"(a[1]), "r"(a[2]), "r"(a[3]), "r"(b0), "r"(b1));
}

// Packed-f32x2 register-tile GEMM
template<int K, int NP, int PITCHX>
__device__ __forceinline__ void gemm2t(const float* in_t, const float* Ws,
                                       float bias, int j, int item0,
                                       unsigned long long* acc) {
    unsigned long long b2 = pack2(bias, bias);
#pragma unroll
    for (int p = 0; p < NP; p++) acc[p] = b2;
    const float* col = in_t + item0;
#pragma unroll 8
    for (int k = 0; k < K; k++) {
        float w = Ws[k * 64 + j];
        unsigned long long ww = pack2(w, w);
        const ulonglong2* row = reinterpret_cast<const ulonglong2*>(col + k * PITCHX);
#pragma unroll
        for (int p = 0; p < NP / 2; p++) {
            ulonglong2 v = row[p];
            fma2(acc[2 * p],     v.x, ww);
            fma2(acc[2 * p + 1], v.y, ww);
        }
    }
}

// Dual-weight GEMM: shares the A-operand pass between two weight matrices.
template<int K, int PITCHX>
__device__ __forceinline__ void gemm2t_dual(const float* in_t,
                                            const float* W1, const float* W2,
                                            float bias1, int j, int item0,
                                            unsigned long long* acc1,
                                            unsigned long long* acc2) {
    unsigned long long b1 = pack2(bias1, bias1);
#pragma unroll
    for (int p = 0; p < 4; p++) { acc1[p] = b1; acc2[p] = 0ull; }
    const float* col = in_t + item0;
#pragma unroll 8
    for (int k = 0; k < K; k++) {
        float w1 = W1[k * 64 + j];
        float w2 = W2[k * 64 + j];
        unsigned long long ww1 = pack2(w1, w1);
        unsigned long long ww2 = pack2(w2, w2);
        const ulonglong2* row = reinterpret_cast<const ulonglong2*>(col + k * PITCHX);
#pragma unroll
        for (int p = 0; p < 2; p++) {
            ulonglong2 v = row[p];
            fma2(acc1[2 * p],     v.x, ww1);
            fma2(acc1[2 * p + 1], v.y, ww1);
            fma2(acc2[2 * p],     v.x, ww2);
            fma2(acc2[2 * p + 1], v.y, ww2);
        }
    }
}

// ---------------- setup kernels ----------------
__global__ void init_kernel(const float* __restrict__ cell_d,
                            float* __restrict__ out, int out_size) {
    int i = blockIdx.x * blockDim.x + threadIdx.x;
    if (i < N_ * 64) { g_dev[i] = 0.f; g_gs[i] = 0.f; }
    if (i < N_) {
        g_wd[i] = cell_d[i * 12];
        g_cnt0[i] = 0; g_cnt1[i] = 0;
    }
    int ntt = N_ * T_;
    if (i < ntt) {
        int pos = ntt + 1 + i;
        if (pos < out_size) out[pos] = 1.0f;
    }
    if (i == 0) {
        g_cnt0[N_] = 0; g_cnt1[N_] = 0;
        g_partial[0] = 0.f; g_partial[1] = 0.f;
    }
}

__global__ void hist_kernel(const int* __restrict__ ei) {
    int i = blockIdx.x * blockDim.x + threadIdx.x;
    if (i < E_) {
        atomicAdd(&g_cnt0[ei[i]], 1);
        atomicAdd(&g_cnt1[ei[E_ + i]], 1);
    }
}

// precompute v1 = demW[c] @ gW1[c], v2 = demb[c] @ gW1[c]
__global__ void gprep_kernel(const float* __restrict__ demW,
                             const float* __restrict__ demb,
                             const float* __restrict__ gW1) {
    int tid = threadIdx.x;
    int c = tid >> 6, j = tid & 63;
    const float* G = gW1 + c * 4096;
    const float* dw = demW + c * 64;
    const float* db = demb + c * 64;
    float a1 = 0.f, a2 = 0.f;
#pragma unroll 8
    for (int k = 0; k < 64; k++) {
        float gv = G[k * 64 + j];
        a1 = fmaf(dw[k], gv, a1);
        a2 = fmaf(db[k], gv, a2);
    }
    g_v1[c * 64 + j] = a1;
    g_v2[c * 64 + j] = a2;
}

__global__ void __launch_bounds__(1024) scan_kernel() {
    __shared__ int wsum[32];
    const int CH = 20;
    int tid = threadIdx.x, lane = tid & 31, wid = tid >> 5;
    for (int a = 0; a < 2; a++) {
        const int* c = a ? g_cnt1 : g_cnt0;
        int* o   = a ? g_off1 : g_off0;
        int* cur = a ? g_cur1 : g_cur0;
        int start = tid * CH;
        int vals[CH];
        int s = 0;
#pragma unroll
        for (int i = 0; i < CH; i++) {
            int idx = start + i;
            int v = (idx < N_) ? c[idx] : 0;
            vals[i] = s; s += v;
        }
        int incl = s;
#pragma unroll
        for (int off = 1; off < 32; off <<= 1) {
            int v = __shfl_up_sync(0xffffffffu, incl, off);
            if (lane >= off) incl += v;
        }
        if (lane == 31) wsum[wid] = incl;
        __syncthreads();
        if (wid == 0) {
            int v = wsum[lane];
            int e = v;
#pragma unroll
            for (int off = 1; off < 32; off <<= 1) {
                int u = __shfl_up_sync(0xffffffffu, e, off);
                if (lane >= off) e += u;
            }
            wsum[lane] = e - v;
        }
        __syncthreads();
        int texcl = wsum[wid] + incl - s;
#pragma unroll
        for (int i = 0; i < CH; i++) {
            int idx = start + i;
            if (idx < N_) {
                int val = texcl + vals[i];
                o[idx] = val; cur[idx] = val;
            }
        }
        if (tid == 1023) o[N_] = texcl + s;
        __syncthreads();
    }
}

__global__ void fill_kernel(const int* __restrict__ ei) {
    int i = blockIdx.x * blockDim.x + threadIdx.x;
    if (i < E_) {
        int a = ei[i], b = ei[E_ + i];
        int s0 = atomicAdd(&g_cur0[a], 1);
        g_pe0[s0] = a; g_pe1[s0] = b;
        int s1 = atomicAdd(&g_cur1[b], 1);
        g_q0[s1] = a;
    }
}

// ---------------- fused node kernels: 64 nodes / 512 threads ----------------
// pre_part: in_t holds cell. Dual GEMM: acc1 = cell@C1+cb1, acc2 = cell@G1;
// u = acc2 + dem*v1[j] + v2[j]; then in_t <- tanh(acc1); msg = in_t@C2 + cb2.
__device__ __forceinline__ void pre_part(float* in_t, const float* C1, const float* C2,
                                         const float* G1,
                                         const float* cb1s, const float* cb2s,
                                         const float* v1, const float* v2,
                                         const float* dem_sh, int base, int j, int g) {
    unsigned long long acc1[4], acc2[4];
    gemm2t_dual<64, NPITCH>(in_t, C1, G1, cb1s[j], j, g * 8, acc1, acc2);
    float v1r = v1[j], v2r = v2[j];
#pragma unroll
    for (int p = 0; p < 4; p++) {
        float lo, hi; unpack2(acc2[p], lo, hi);
        int item = g * 8 + 2 * p;
        int n0 = base + item;
        if (n0 < N_)     g_u[n0 * 64 + j]       = lo + dem_sh[item] * v1r + v2r;
        if (n0 + 1 < N_) g_u[(n0 + 1) * 64 + j] = hi + dem_sh[item + 1] * v1r + v2r;
    }
    __syncthreads();   // all gemm reads of cell done before overwrite
#pragma unroll
    for (int p = 0; p < 4; p++) {
        float lo, hi; unpack2(acc1[p], lo, hi);
        *reinterpret_cast<unsigned long long*>(in_t + j * NPITCH + g * 8 + 2 * p)
            = pack2(tanha(lo), tanha(hi));
    }
    __syncthreads();
    gemm2t<64, 4, NPITCH>(in_t, C2, cb2s[j], j, g * 8, acc1);
#pragma unroll
    for (int p = 0; p < 4; p++) {
        float lo, hi; unpack2(acc1[p], lo, hi);
        int n0 = base + g * 8 + 2 * p;
        if (n0 < N_)     g_msg[n0 * 64 + j]       = lo;
        if (n0 + 1 < N_) g_msg[(n0 + 1) * 64 + j] = hi;
    }
}

__device__ __forceinline__ void dql_part(float* in_t, const float* Wds, const float* bds,
                                         float* dsw, int base, int w, int lane, int do_tanh) {
#pragma unroll
    for (int r = 0; r < 4; r++) {
        int e = w * 4 + r;
        int node = base + e;
        if (node < N_) {
            float i0 = 0.f, i1 = 0.f;
            int s0 = g_off1[node], s1 = g_off1[node + 1];
            for (int s = s0; s < s1; s++) {
                int m = g_q0[s];
                i0 += g_dev[m * 64 + lane];
                i1 += g_dev[m * 64 + 32 + lane];
            }
            float d0 = i0 - g_dev[node * 64 + lane];
            float d1 = i1 - g_dev[node * 64 + 32 + lane];
            dsw[lane] = d0; dsw[32 + lane] = d1;
            __syncwarp();
            float a0 = bds[lane], a1 = bds[32 + lane];
#pragma unroll 4
            for (int k = 0; k < 64; k++) {
                float dv = dsw[k];
                a0 = fmaf(dv, Wds[k * 64 + lane], a0);
                a1 = fmaf(dv, Wds[k * 64 + 32 + lane], a1);
            }
            float c0 = g_cell[node * 64 + lane] + a0;
            float c1 = g_cell[node * 64 + 32 + lane] + a1;
            if (do_tanh) { c0 = tanha(c0); c1 = tanha(c1); }
            g_cell[node * 64 + lane] = c0;
            g_cell[node * 64 + 32 + lane] = c1;
            in_t[lane * NPITCH + e] = c0;
            in_t[(lane + 32) * NPITCH + e] = c1;
        } else {
            in_t[lane * NPITCH + e] = 0.f;
            in_t[(lane + 32) * NPITCH + e] = 0.f;
        }
        __syncwarp();
    }
}

// rain (3 layers) + conservation-0 pre (u, msg)
#define RP_SMEM ((4352 + 2048 + 4096 * 4 + 384 + 64 + 128) * 4)
__global__ void __launch_bounds__(512) rainpre_kernel(
    const float* __restrict__ cell_d, const float* __restrict__ cell_s,
    const float* __restrict__ rW1, const float* __restrict__ rb1,
    const float* __restrict__ rW2, const float* __restrict__ rb2,
    const float* __restrict__ rW3, const float* __restrict__ rb3,
    const float* __restrict__ cW1, const float* __restrict__ cb1,
    const float* __restrict__ cW2, const float* __restrict__ cb2,
    const float* __restrict__ gW1, int t)
{
    extern __shared__ __align__(16) float sf[];
    float* in_t = sf;
    float* W2r = sf + 4352;
    float* W3r = sf + 6400;
    float* C1  = sf + 10496;
    float* C2  = sf + 14592;
    float* G1  = sf + 18688;
    float* b2r = sf + 22784;
    float* b3r = sf + 22848;
    float* cb1s = sf + 22912;
    float* cb2s = sf + 22976;
    float* dem_sh = sf + 23040;
    float* v1s = sf + 23104;
    float* v2s = sf + 23168;
    int tid = threadIdx.x;
    int base = blockIdx.x * NT;
    for (int i = tid; i < 2048; i += 512) W2r[i] = rW2[i];
    for (int i = tid; i < 4096; i += 512) {
        W3r[i] = rW3[i]; C1[i] = cW1[i]; C2[i] = cW2[i]; G1[i] = gW1[i];
    }
    if (tid < 64) {
        b2r[tid] = rb2[tid]; b3r[tid] = rb3[tid];
        cb1s[tid] = cb1[tid]; cb2s[tid] = cb2[tid];
        v1s[tid] = g_v1[tid]; v2s[tid] = g_v2[tid];
        int n = base + tid;
        dem_sh[tid] = (n < N_) ? cell_s[n * 2] : 0.f;
    }
    {
        int item = tid & 63, fb = tid >> 6;
        int n = base + item;
        float w = 0.f, r = 0.f;
        if (n < N_) { w = g_wd[n]; r = cell_d[n * 12 + t * 3 + 2]; }
#pragma unroll
        for (int u = 0; u < 4; u++) {
            int f = fb * 4 + u;
            in_t[f * NPITCH + item] = tanha(w * rW1[f] + r * rW1[32 + f] + rb1[f]);
        }
    }
    __syncthreads();
    int j = tid & 63, g = tid >> 6;
    unsigned long long acc[4];
    gemm2t<32, 4, NPITCH>(in_t, W2r, b2r[j], j, g * 8, acc);
    __syncthreads();
#pragma unroll
    for (int p = 0; p < 4; p++) {
        float lo, hi; unpack2(acc[p], lo, hi);
        *reinterpret_cast<unsigned long long*>(in_t + j * NPITCH + g * 8 + 2 * p)
            = pack2(tanha(lo), tanha(hi));
    }
    __syncthreads();
    gemm2t<64, 4, NPITCH>(in_t, W3r, b3r[j], j, g * 8, acc);
    __syncthreads();
#pragma unroll
    for (int p = 0; p < 4; p++) {
        float lo, hi; unpack2(acc[p], lo, hi);
        int i0 = g * 8 + 2 * p;
        int n0 = base + i0;
        if (n0 < N_)     g_cell[n0 * 64 + j]       = lo;
        if (n0 + 1 < N_) g_cell[(n0 + 1) * 64 + j] = hi;
        in_t[j * NPITCH + i0] = lo;
        in_t[j * NPITCH + i0 + 1] = hi;
    }
    __syncthreads();
    pre_part(in_t, C1, C2, G1, cb1s, cb2s, v1s, v2s, dem_sh, base, j, g);
}

// dql(c=0, tanh) + conservation-1 pre (u, msg)
#define DP_SMEM ((4352 + 4096 * 4 + 1024 + 320 + 128) * 4)
__global__ void __launch_bounds__(512) dqlpre_kernel(
    const float* __restrict__ cell_s,
    const float* __restrict__ dqW, const float* __restrict__ dqb,
    const float* __restrict__ cW1, const float* __restrict__ cb1,
    const float* __restrict__ cW2, const float* __restrict__ cb2,
    const float* __restrict__ gW1)
{
    extern __shared__ __align__(16) float sf[];
    float* in_t = sf;
    float* Wds = sf + 4352;
    float* C1  = sf + 8448;
    float* C2  = sf + 12544;
    float* G1  = sf + 16640;
    float* ds  = sf + 20736;
    float* bds = sf + 21760;
    float* cb1s = sf + 21824;
    float* cb2s = sf + 21888;
    float* dem_sh = sf + 21952;
    float* v1s = sf + 22016;
    float* v2s = sf + 22080;
    int tid = threadIdx.x;
    int base = blockIdx.x * NT;
    for (int i = tid; i < 4096; i += 512) {
        Wds[i] = dqW[i]; C1[i] = cW1[i]; C2[i] = cW2[i]; G1[i] = gW1[i];
    }
    if (tid < 64) {
        bds[tid] = dqb[tid];
        cb1s[tid] = cb1[tid]; cb2s[tid] = cb2[tid];
        v1s[tid] = g_v1[64 + tid]; v2s[tid] = g_v2[64 + tid];
        int n = base + tid;
        dem_sh[tid] = (n < N_) ? cell_s[n * 2] : 0.f;
    }
    __syncthreads();
    int w = tid >> 5, lane = tid & 31;
    dql_part(in_t, Wds, bds, ds + w * 64, base, w, lane, 1);
    __syncthreads();
    int j = tid & 63, g = tid >> 6;
    pre_part(in_t, C1, C2, G1, cb1s, cb2s, v1s, v2s, dem_sh, base, j, g);
}

// dql(c=1, no tanh) + elev + losses
#define DE_SMEM ((4352 + 4096 * 2 + 1024 + 192 + 1) * 4)
__global__ void __launch_bounds__(512) dqlelev_kernel(
    const float* __restrict__ cell_d,
    const float* __restrict__ dqW, const float* __restrict__ dqb,
    const float* __restrict__ eW1, const float* __restrict__ eb1,
    const float* __restrict__ eW2, const float* __restrict__ eb2,
    float* __restrict__ out, int t, int out_size)
{
    extern __shared__ __align__(16) float sf[];
    float* in_t = sf;
    float* Wds = sf + 4352;
    float* W1s = sf + 8448;
    float* ds  = sf + 12544;
    float* bds = sf + 13568;
    float* b1s = sf + 13632;
    float* w2s = sf + 13696;
    float* b2p = sf + 13760;
    int tid = threadIdx.x;
    int base = blockIdx.x * NT;
    for (int i = tid; i < 4096; i += 512) { Wds[i] = dqW[i]; W1s[i] = eW1[i]; }
    if (tid < 64) {
        bds[tid] = dqb[tid];
        b1s[tid] = eb1[tid]; w2s[tid] = eW2[tid];
    }
    if (tid == 0) b2p[0] = eb2[0];
    __syncthreads();
    int w = tid >> 5, lane = tid & 31;
    dql_part(in_t, Wds, bds, ds + w * 64, base, w, lane, 0);
    __syncthreads();
    int j = tid & 63, g = tid >> 6;
    unsigned long long acc[4];
    gemm2t<64, 4, NPITCH>(in_t, W1s, b1s[j], j, g * 8, acc);
    __syncthreads();
#pragma unroll
    for (int p = 0; p < 4; p++) {
        float lo, hi; unpack2(acc[p], lo, hi);
        *reinterpret_cast<unsigned long long*>(in_t + j * NPITCH + g * 8 + 2 * p)
            = pack2(tanha(lo), tanha(hi));
    }
    __syncthreads();
    if (tid < 64) {
        int e = tid, n = base + e;
        float hub = 0.f, nz = 0.f;
        if (n < N_) {
            float a = b2p[0];
#pragma unroll 8
            for (int k = 0; k < 64; k++) a = fmaf(in_t[k * NPITCH + e], w2s[k], a);
            float wv = g_wd[n] + a;
            g_wd[n] = wv;
            int pos = n * 3 + t;
            if (pos < out_size) out[pos] = wv;
            float target = cell_d[n * 12 + (t + 1) * 3];
            float diff = target - wv;
            float ad = fabsf(diff);
            hub = (ad < 1.f) ? ad : diff * diff;
            nz = fmaxf(-wv, 0.f);
        }
#pragma unroll
        for (int o = 16; o > 0; o >>= 1) {
            hub += __shfl_down_sync(0xffffffffu, hub, o);
            nz  += __shfl_down_sync(0xffffffffu, nz, o);
        }
        if ((tid & 31) == 0) {
            atomicAdd(&g_partial[0], hub);
            atomicAdd(&g_partial[1], nz);
        }
    }
}

// ---------------- persistent single-layer edge gate kernel (round-16 exact) ----------------
#define ES_S   0
#define ES_W2  (256 * SP)
#define ES_B1  (ES_W2 + 4096)
#define ES_B2  (ES_B1 + 64)
#define ES_NID (ES_B2 + 64)
#define E_SMEM ((ES_NID + 256) * 4)

__global__ void __launch_bounds__(256, 2) edge_gate_mma_kernel(
    const float* __restrict__ gb1,
    const float* __restrict__ gW2, const float* __restrict__ gb2)
{
    extern __shared__ __align__(16) uint32_t sm[];
    uint32_t* S = sm + ES_S;
    uint2* W2b = reinterpret_cast<uint2*>(sm + ES_W2);
    float* b1s = reinterpret_cast<float*>(sm + ES_B1);
    float* b2s = reinterpret_cast<float*>(sm + ES_B2);
    int* nid = reinterpret_cast<int*>(sm + ES_NID);

    int tid = threadIdx.x;
    for (int i = tid; i < 2048; i += 256) {
        int l = i & 31, ksnt = i >> 5;
        int nt = ksnt >> 3, ks = ksnt & 7;
        int n = nt * 8 + (l >> 2);
        int k0 = ks * 8 + (l & 3);
        W2b[i] = make_uint2(f2tf32(gW2[k0 * 64 + n]), f2tf32(gW2[(k0 + 4) * 64 + n]));
    }
    if (tid < 64) { b1s[tid] = gb1[tid]; b2s[tid] = gb2[tid]; }

    int w = tid >> 5, l = tid & 31;
    int g = l >> 2, t = l & 3;
    int erow = w * 32;

    for (int tile = blockIdx.x; tile < NTILES; tile += gridDim.x) {
        __syncthreads();
        int base = tile * EB;
#pragma unroll
        for (int eo = 0; eo < EB; eo += 128) {
            int e = (tid >> 1) + eo, half = tid & 1;
            int slot = base + e;
            int c0 = half * 32;
            if (slot < E_) {
                int n0 = g_pe0[slot], n1 = g_pe1[slot];
                if (half == 0) nid[e] = n0;
                const float4* pa = reinterpret_cast<const float4*>(g_u + n0 * 64 + c0);
                const float4* pc = reinterpret_cast<const float4*>(g_u + n1 * 64 + c0);
#pragma unroll
                for (int q = 0; q < 8; q++) {
                    float4 a = pa[q], c = pc[q];
                    int f = c0 + q * 4;
                    uint4 v;
                    v.x = f2tf32(tanha(a.x - c.x + b1s[f + 0]));
                    v.y = f2tf32(tanha(a.y - c.y + b1s[f + 1]));
                    v.z = f2tf32(tanha(a.z - c.z + b1s[f + 2]));
                    v.w = f2tf32(tanha(a.w - c.w + b1s[f + 3]));
                    *reinterpret_cast<uint4*>(S + e * SP + f) = v;
                }
            } else {
                if (half == 0) nid[e] = -1;
                uint4 z = {0u, 0u, 0u, 0u};
#pragma unroll
                for (int q = 0; q < 8; q++)
                    *reinterpret_cast<uint4*>(S + e * SP + c0 + q * 4) = z;
            }
        }
        __syncthreads();

        uint32_t a[2][8][4];
#pragma unroll
        for (int rg = 0; rg < 2; rg++)
#pragma unroll
            for (int ks = 0; ks < 8; ks++) {
                const uint32_t* p = S + (erow + rg * 16 + g) * SP + t + ks * 8;
                a[rg][ks][0] = p[0];
                a[rg][ks][1] = p[8 * SP];
                a[rg][ks][2] = p[4];
                a[rg][ks][3] = p[8 * SP + 4];
            }
#pragma unroll
        for (int nt = 0; nt < 8; nt++) {
            uint2 b[8];
#pragma unroll
            for (int ks = 0; ks < 8; ks++) b[ks] = W2b[((nt * 8 + ks) << 5) + l];
            float bl = b2s[nt * 8 + 2 * t], bh = b2s[nt * 8 + 2 * t + 1];
#pragma unroll
            for (int rg = 0; rg < 2; rg++) {
                float acc[4] = {bl, bh, bl, bh};
#pragma unroll
                for (int ks = 0; ks < 8; ks++)
                    mma_tf32(acc, a[rg][ks], b[ks].x, b[ks].y);
                uint32_t* s0 = S + (erow + rg * 16 + g) * SP + nt * 8 + 2 * t;
                *reinterpret_cast<uint2*>(s0) = make_uint2(__float_as_uint(sigm_fast(acc[0])),
                                                           __float_as_uint(sigm_fast(acc[1])));
                *reinterpret_cast<uint2*>(s0 + 8 * SP) = make_uint2(__float_as_uint(sigm_fast(acc[2])),
                                                                    __float_as_uint(sigm_fast(acc[3])));
            }
        }
        __syncthreads();
        {
            int col = tid & 63, q = tid >> 6;
            int r0 = q * 64, r1 = r0 + 64;
            float accv = 0.f;
            int cur = nid[r0];
#pragma unroll 8
            for (int r = r0; r < r1; r++) {
                int nd = nid[r];
                float v = __uint_as_float(S[r * SP + col]);
                if (nd != cur) {
                    if (cur >= 0) atomicAdd(g_gs + (size_t)cur * 64 + col, accv);
                    accv = 0.f; cur = nd;
                }
                accv += v;
            }
            if (cur >= 0) atomicAdd(g_gs + (size_t)cur * 64 + col, accv);
        }
    }
}

// dev += msg * gs ; gs = 0
__global__ void __launch_bounds__(256) devupd_kernel() {
    int i = blockIdx.x * blockDim.x + threadIdx.x;
    if (i >= N_ * 16) return;
    float4* dv = reinterpret_cast<float4*>(g_dev) + i;
    float4* gs = reinterpret_cast<float4*>(g_gs) + i;
    const float4* ms = reinterpret_cast<const float4*>(g_msg) + i;
    float4 d = *dv, s = *gs, m = *ms;
    d.x = fmaf(m.x, s.x, d.x);
    d.y = fmaf(m.y, s.y, d.y);
    d.z = fmaf(m.z, s.z, d.z);
    d.w = fmaf(m.w, s.w, d.w);
    *dv = d;
    *gs = make_float4(0.f, 0.f, 0.f, 0.f);
}

__global__ void tail_kernel(float* __restrict__ out, int out_size) {
    int ntt = N_ * T_;
    if (ntt < out_size)         out[ntt]         = g_partial[0] * (0.5f / (float)N_);
    if (2 * ntt + 1 < out_size) out[2 * ntt + 1] = g_partial[1] * (1.0f / (float)N_);
}

// ---------------- launcher ----------------
extern "C" void kernel_launch(void* const* d_in, const int* in_sizes, int n_in,
                              void* d_out, int out_size) {
    const float* cell_d = (const float*)d_in[0];
    const float* cell_s = (const float*)d_in[1];
    const int*   eidx   = (const int*)d_in[3];
    const float* rW1 = (const float*)d_in[5];
    const float* rb1 = (const float*)d_in[6];
    const float* rW2 = (const float*)d_in[7];
    const float* rb2 = (const float*)d_in[8];
    const float* rW3 = (const float*)d_in[9];
    const float* rb3 = (const float*)d_in[10];
    const float* eW1 = (const float*)d_in[11];
    const float* eb1 = (const float*)d_in[12];
    const float* eW2 = (const float*)d_in[13];
    const float* eb2 = (const float*)d_in[14];
    const float* demW = (const float*)d_in[15];
    const float* demb = (const float*)d_in[16];
    const float* cW1 = (const float*)d_in[17];
    const float* cb1 = (const float*)d_in[18];
    const float* cW2 = (const float*)d_in[19];
    const float* cb2 = (const float*)d_in[20];
    const float* gW1 = (const float*)d_in[21];
    const float* gb1 = (const float*)d_in[22];
    const float* gW2 = (const float*)d_in[23];
    const float* gb2 = (const float*)d_in[24];
    const float* dqW = (const float*)d_in[25];
    const float* dqb = (const float*)d_in[26];
    float* out = (float*)d_out;

    cudaFuncSetAttribute(edge_gate_mma_kernel,
                         cudaFuncAttributeMaxDynamicSharedMemorySize, E_SMEM);
    cudaFuncSetAttribute(rainpre_kernel,
                         cudaFuncAttributeMaxDynamicSharedMemorySize, RP_SMEM);
    cudaFuncSetAttribute(dqlpre_kernel,
                         cudaFuncAttributeMaxDynamicSharedMemorySize, DP_SMEM);
    cudaFuncSetAttribute(dqlelev_kernel,
                         cudaFuncAttributeMaxDynamicSharedMemorySize, DE_SMEM);

    init_kernel<<<(N_ * 64 + 255) / 256, 256>>>(cell_d, out, out_size);
    hist_kernel<<<(E_ + 255) / 256, 256>>>(eidx);
    gprep_kernel<<<1, 128>>>(demW, demb, gW1);
    scan_kernel<<<1, 1024>>>();
    fill_kernel<<<(E_ + 255) / 256, 256>>>(eidx);

    const int devBlocks = (N_ * 16 + 255) / 256;

    for (int t = 0; t < T_; t++) {
        rainpre_kernel<<<NBLK, 512, RP_SMEM>>>(cell_d, cell_s,
            rW1, rb1, rW2, rb2, rW3, rb3,
            cW1, cb1, cW2, cb2, gW1, t);
        edge_gate_mma_kernel<<<EGRID, 256, E_SMEM>>>(gb1, gW2, gb2);
        devupd_kernel<<<devBlocks, 256>>>();
        dqlpre_kernel<<<NBLK, 512, DP_SMEM>>>(cell_s,
            dqW, dqb,
            cW1 + 4096, cb1 + 64, cW2 + 4096, cb2 + 64,
            gW1 + 4096);
        edge_gate_mma_kernel<<<EGRID, 256, E_SMEM>>>(gb1 + 64, gW2 + 4096, gb2 + 64);
        devupd_kernel<<<devBlocks, 256>>>();
        dqlelev_kernel<<<NBLK, 512, DE_SMEM>>>(cell_d,
            dqW + 4096, dqb + 64, eW1, eb1, eW2, eb2, out, t, out_size);
    }
    tail_kernel<<<1, 1>>>(out, out_size);
}